// round 1
// baseline (speedup 1.0000x reference)
#include <cuda_runtime.h>
#include <cuda_bf16.h>

// ---------------------------------------------------------------------------
// MAUCHLoss: fused sigmoid + per-category AUC hinge + double-sigmoid CEL.
//   sig   = sigmoid(x)
//   cel_e = l*sig - softplus(sig)         (== l*log(s2) + (1-l)*log(1-s2))
//   per col c: Ssig[c], Slsig[c], Sl[c]
//   penalty[c] = 1 - Slsig/npos + (Ssig-Slsig)/(B-npos)
//   out[0] = cel + 0.1*(sum(penalty)/15);  out[1] = 0.1*penalty[14]
// softplus(u) on u in (0,1):  ln2 + u/2 + w*(1/8 - w/192 + w^2/2880), w=u^2
//   -> per-element we only accumulate wp = w*p(w); ln2 & u/2 terms fold into
//      element count and sum(sig).
// ---------------------------------------------------------------------------

#define NBLK   304
#define NTHR   256
#define NACC   46          // 15 Ssig + 15 Slsig + 15 Sl + 1 Swp

__device__ float g_scratch[NACC * NBLK];

__device__ __forceinline__ float fast_ex2(float a) {
    float r; asm("ex2.approx.ftz.f32 %0, %1;" : "=f"(r) : "f"(a)); return r;
}
__device__ __forceinline__ float fast_rcp(float a) {
    float r; asm("rcp.approx.ftz.f32 %0, %1;" : "=f"(r) : "f"(a)); return r;
}

__device__ __forceinline__ void elem_update(float x, float lb, float* acc, int col) {
    const float LOG2E = 1.4426950408889634f;
    float t   = fast_ex2(-LOG2E * x);       // e^{-x}
    float sig = fast_rcp(1.0f + t);         // sigmoid(x)
    float ls  = lb * sig;
    float w   = sig * sig;
    float p   = fmaf(fmaf(3.4722222e-4f, w, -5.2083333e-3f), w, 0.125f);
    acc[col]      += sig;
    acc[15 + col] += ls;
    acc[30 + col] += lb;
    acc[45]        = fmaf(w, p, acc[45]);   // accumulate w*p(w)
}

__global__ __launch_bounds__(NTHR)
void mauc_main(const float4* __restrict__ outp, const float4* __restrict__ labp,
               int nchunk)
{
    float acc[NACC];
#pragma unroll
    for (int i = 0; i < NACC; i++) acc[i] = 0.0f;

    const int stride = gridDim.x * blockDim.x;
#pragma unroll 1
    for (int c = blockIdx.x * blockDim.x + threadIdx.x; c < nchunk; c += stride) {
        const float4* o = outp + (size_t)c * 15;
        const float4* l = labp + (size_t)c * 15;
        float4 xo[15], xl[15];
#pragma unroll
        for (int i = 0; i < 15; i++) xo[i] = o[i];
#pragma unroll
        for (int i = 0; i < 15; i++) xl[i] = l[i];

#pragma unroll
        for (int i = 0; i < 15; i++) {
            elem_update(xo[i].x, xl[i].x, acc, (4 * i + 0) % 15);
            elem_update(xo[i].y, xl[i].y, acc, (4 * i + 1) % 15);
            elem_update(xo[i].z, xl[i].z, acc, (4 * i + 2) % 15);
            elem_update(xo[i].w, xl[i].w, acc, (4 * i + 3) % 15);
        }
    }

    // ---- block reduction: warp shfl, then per-warp rows in smem ----
    const unsigned FULL = 0xFFFFFFFFu;
#pragma unroll
    for (int v = 0; v < NACC; v++) {
        float s = acc[v];
        s += __shfl_down_sync(FULL, s, 16);
        s += __shfl_down_sync(FULL, s, 8);
        s += __shfl_down_sync(FULL, s, 4);
        s += __shfl_down_sync(FULL, s, 2);
        s += __shfl_down_sync(FULL, s, 1);
        acc[v] = s;
    }

    __shared__ float sm[NTHR / 32][NACC];
    const int wid  = threadIdx.x >> 5;
    const int lane = threadIdx.x & 31;
    if (lane == 0) {
#pragma unroll
        for (int v = 0; v < NACC; v++) sm[wid][v] = acc[v];
    }
    __syncthreads();
    if (threadIdx.x < NACC) {
        float s = 0.0f;
#pragma unroll
        for (int w = 0; w < NTHR / 32; w++) s += sm[w][threadIdx.x];
        g_scratch[threadIdx.x * NBLK + blockIdx.x] = s;
    }
}

__global__ void mauc_final(float* __restrict__ out,
                           const float* __restrict__ outp,
                           const float* __restrict__ labp,
                           int n, int nchunk)
{
    __shared__ float tot[NACC];
    const unsigned FULL = 0xFFFFFFFFu;
    const int wid  = threadIdx.x >> 5;     // 16 warps (512 threads)
    const int lane = threadIdx.x & 31;

    for (int v = wid; v < NACC; v += 16) {
        float s = 0.0f;
        for (int b = lane; b < NBLK; b += 32) s += g_scratch[v * NBLK + b];
        s += __shfl_down_sync(FULL, s, 16);
        s += __shfl_down_sync(FULL, s, 8);
        s += __shfl_down_sync(FULL, s, 4);
        s += __shfl_down_sync(FULL, s, 2);
        s += __shfl_down_sync(FULL, s, 1);
        if (lane == 0) tot[v] = s;
    }
    __syncthreads();

    if (threadIdx.x == 0) {
        double ssig[15], slsig[15], sl[15];
        double swp = (double)tot[45];
        for (int c = 0; c < 15; c++) {
            ssig[c]  = (double)tot[c];
            slsig[c] = (double)tot[15 + c];
            sl[c]    = (double)tot[30 + c];
        }
        // tail elements (n % 60 != 0) — none for this shape, kept for safety
        const float LOG2E = 1.4426950408889634f;
        for (int idx = nchunk * 60; idx < n; idx++) {
            int col  = idx % 15;
            float x  = outp[idx];
            float lb = labp[idx];
            float t   = fast_ex2(-LOG2E * x);
            float sig = fast_rcp(1.0f + t);
            float w   = sig * sig;
            float p   = fmaf(fmaf(3.4722222e-4f, w, -5.2083333e-3f), w, 0.125f);
            ssig[col]  += sig;
            slsig[col] += lb * sig;
            sl[col]    += lb;
            swp        += w * p;
        }

        const double LN2 = 0.6931471805599453;
        double N   = (double)n;
        double Bf  = N / 15.0;

        double sum_sig_all  = 0.0, sum_lsig_all = 0.0;
        double sum_term = 0.0, pen14 = 0.0;
        for (int c = 0; c < 15; c++) {
            sum_sig_all  += ssig[c];
            sum_lsig_all += slsig[c];
            double np = sl[c];
            double nn = Bf - np;
            double mp = (np > 0.0) ? slsig[c] / fmax(np, 1.0) : 0.0;
            double mn = (nn > 0.0) ? (ssig[c] - slsig[c]) / fmax(nn, 1.0) : 0.0;
            double pen = 1.0 - mp + mn;
            sum_term += pen;
            if (c == 14) pen14 = pen;
        }
        // sum softplus(sig) = N*ln2 + 0.5*sum(sig) + sum(w*p)
        double sp_total = N * LN2 + 0.5 * sum_sig_all + swp;
        double cel = (sp_total - sum_lsig_all) / N;   // -(sum(l*sig - sp))/N
        out[0] = (float)(cel + 0.1 * (sum_term / 15.0));
        out[1] = (float)(0.1 * pen14);
    }
}

extern "C" void kernel_launch(void* const* d_in, const int* in_sizes, int n_in,
                              void* d_out, int out_size)
{
    const float* outp = (const float*)d_in[0];
    const float* labp = (const float*)d_in[1];
    int n = in_sizes[0];
    int nchunk = n / 60;

    mauc_main<<<NBLK, NTHR>>>((const float4*)outp, (const float4*)labp, nchunk);
    mauc_final<<<1, 512>>>((float*)d_out, outp, labp, n, nchunk);
}